// round 2
// baseline (speedup 1.0000x reference)
#include <cuda_runtime.h>
#include <math.h>
#include <stdint.h>

// Problem shape constants
#define B_   8
#define C_   256
#define H_   128
#define W_   128
#define HW_  16384          // H_*W_
#define NT_  131072         // B_*HW_
#define C2_  512            // 2*C_

// ---------------------------------------------------------------------------
// Scratch (device globals; allocation-free rule)
// ---------------------------------------------------------------------------
__device__ float g_xt  [NT_ * C_];        // x token-major (B,H,W,C)      134 MB
__device__ float g_qkv [NT_ * 3 * C_];    // qkv per token                403 MB
__device__ float g_h   [NT_ * C2_];       // fc1 out / gelu-normed        268 MB
__device__ float g_mlp [NT_ * C_];        // fc2 out                      134 MB
__device__ float g_vec0[NT_ * C_];        // attention out, branch g      134 MB
__device__ float g_vec1[NT_ * C_];        // attention out, branch w      134 MB
__device__ float g_bit0[NT_];
__device__ float g_bit1[NT_];
__device__ float g_sums[2 * B_ * C2_];    // [0:4096) sum, [4096:8192) sumsq

// ---------------------------------------------------------------------------
// Transpose x (B,C,H,W) -> xt (B,H,W,C)
// ---------------------------------------------------------------------------
__global__ __launch_bounds__(256) void transpose_kernel(const float* __restrict__ x,
                                                        float* __restrict__ xt) {
    __shared__ float tile[32][33];
    const int bh = blockIdx.z;                 // b*H + h
    const int b  = bh >> 7, hh = bh & 127;
    const int cb = blockIdx.y << 5, wb = blockIdx.x << 5;
    const int tx = threadIdx.x, ty = threadIdx.y;     // (32, 8)
    const float* src = x + (((size_t)b * C_ + cb) * H_ + hh) * W_ + wb;
#pragma unroll
    for (int i = 0; i < 4; i++)
        tile[ty + i * 8][tx] = src[(size_t)(ty + i * 8) * HW_ + tx];
    __syncthreads();
    float* dst = xt + (((size_t)b * H_ + hh) * W_ + wb) * C_ + cb;
#pragma unroll
    for (int i = 0; i < 4; i++)
        dst[(size_t)(ty + i * 8) * C_ + tx] = tile[tx][ty + i * 8];
}

// ---------------------------------------------------------------------------
// SGEMM: C = A(MxK) * B(KxN) [+ bias], row-major. Tile 128x128x16, 8x8/thread.
// Double-buffered smem with register-staged prefetch.
// Grid: (N/128, M/128), 256 threads.
// ---------------------------------------------------------------------------
__global__ __launch_bounds__(256) void sgemm(const float* __restrict__ A,
                                             const float* __restrict__ Bm,
                                             const float* __restrict__ bias,
                                             float* __restrict__ Cm,
                                             int N, int K) {
    __shared__ float As[2][16][128];
    __shared__ float Bs[2][16][128];
    const int tid = threadIdx.x;
    const int bm = blockIdx.y << 7, bn = blockIdx.x << 7;
    const int tx = tid & 15, ty = tid >> 4;

    float acc[8][8];
#pragma unroll
    for (int i = 0; i < 8; i++)
#pragma unroll
        for (int j = 0; j < 8; j++) acc[i][j] = 0.f;

    // Per-thread load coordinates (two rounds of 256 threads each)
    float4 la[2], lb[2];

    auto load_tiles = [&](int k0) {
#pragma unroll
        for (int r = 0; r < 2; r++) {
            int idx = tid + (r << 8);
            int m = idx >> 2, kc = (idx & 3) << 2;
            la[r] = *(const float4*)(A + (size_t)(bm + m) * K + k0 + kc);
            int kr = idx >> 5, nc = (idx & 31) << 2;
            lb[r] = *(const float4*)(Bm + (size_t)(k0 + kr) * N + bn + nc);
        }
    };
    auto store_tiles = [&](int buf) {
#pragma unroll
        for (int r = 0; r < 2; r++) {
            int idx = tid + (r << 8);
            int m = idx >> 2, kc = (idx & 3) << 2;
            As[buf][kc + 0][m] = la[r].x;
            As[buf][kc + 1][m] = la[r].y;
            As[buf][kc + 2][m] = la[r].z;
            As[buf][kc + 3][m] = la[r].w;
            int kr = idx >> 5, nc = (idx & 31) << 2;
            *(float4*)&Bs[buf][kr][nc] = lb[r];
        }
    };
    auto compute = [&](int buf) {
#pragma unroll
        for (int kk = 0; kk < 16; kk++) {
            float a[8], b[8];
            *(float4*)(a)     = *(const float4*)&As[buf][kk][ty << 3];
            *(float4*)(a + 4) = *(const float4*)&As[buf][kk][(ty << 3) + 4];
            *(float4*)(b)     = *(const float4*)&Bs[buf][kk][tx << 3];
            *(float4*)(b + 4) = *(const float4*)&Bs[buf][kk][(tx << 3) + 4];
#pragma unroll
            for (int i = 0; i < 8; i++)
#pragma unroll
                for (int j = 0; j < 8; j++)
                    acc[i][j] = fmaf(a[i], b[j], acc[i][j]);
        }
    };

    // Prologue: stage first tile
    load_tiles(0);
    store_tiles(0);
    __syncthreads();

    int buf = 0;
    for (int k0 = 16; k0 < K; k0 += 16) {
        load_tiles(k0);        // LDG next tile (latency hidden under compute)
        compute(buf);          // FFMA on current tile
        store_tiles(buf ^ 1);  // STS staged regs into the other buffer
        __syncthreads();
        buf ^= 1;
    }
    compute(buf);              // epilogue tile

    float bb[8];
#pragma unroll
    for (int j = 0; j < 8; j++) bb[j] = bias ? bias[bn + (tx << 3) + j] : 0.f;
#pragma unroll
    for (int i = 0; i < 8; i++) {
        float* outp = Cm + (size_t)(bm + (ty << 3) + i) * N + bn + (tx << 3);
        float4 v0 = make_float4(acc[i][0] + bb[0], acc[i][1] + bb[1],
                                acc[i][2] + bb[2], acc[i][3] + bb[3]);
        float4 v1 = make_float4(acc[i][4] + bb[4], acc[i][5] + bb[5],
                                acc[i][6] + bb[6], acc[i][7] + bb[7]);
        *(float4*)outp = v0;
        *(float4*)(outp + 4) = v1;
    }
}

// ---------------------------------------------------------------------------
// Windowed attention: block = (head, window). 64 tokens, hd=64, scale=1/8.
// Dynamic smem: q,k,v,S each [64][68] floats = 69632 B.
// ---------------------------------------------------------------------------
#define AP 68
__global__ __launch_bounds__(256) void attn_kernel(const float* __restrict__ qkv,
                                                   float* __restrict__ vec) {
    extern __shared__ float sm[];
    float* qs = sm;
    float* ks = sm + 64 * AP;
    float* vs = sm + 2 * 64 * AP;
    float* Ss = sm + 3 * 64 * AP;

    const int t = threadIdx.x;
    const int head = blockIdx.x;
    const int win  = blockIdx.y;
    const int b = win >> 8, wx = (win >> 4) & 15, wy = win & 15;
    const int rowbase = b * HW_ + ((wx << 3) * W_) + (wy << 3);
    // token i -> global row = rowbase + (i>>3)*W_ + (i&7)

#pragma unroll
    for (int r = 0; r < 4; r++) {
        int idx = t + (r << 8);
        int i = idx >> 4, fc = (idx & 15) << 2;
        const float* src = qkv + (size_t)(rowbase + (i >> 3) * W_ + (i & 7)) * 768
                               + (head << 6) + fc;
        float4 qv = *(const float4*)src;
        float4 kv = *(const float4*)(src + 256);
        float4 vv = *(const float4*)(src + 512);
        qv.x *= 0.125f; qv.y *= 0.125f; qv.z *= 0.125f; qv.w *= 0.125f;
        *(float4*)&qs[i * AP + fc] = qv;
        *(float4*)&ks[i * AP + fc] = kv;
        *(float4*)&vs[i * AP + fc] = vv;
    }
    __syncthreads();

    const int rid = t >> 4, cid = t & 15;
    const int i0 = rid << 2, j0 = cid << 2;

    // S = q @ k^T (scaled), 4x4 per thread
    {
        float s[4][4];
#pragma unroll
        for (int i = 0; i < 4; i++)
#pragma unroll
            for (int j = 0; j < 4; j++) s[i][j] = 0.f;
        for (int c = 0; c < 64; c += 4) {
            float4 aq[4], bk[4];
#pragma unroll
            for (int ii = 0; ii < 4; ii++) aq[ii] = *(const float4*)&qs[(i0 + ii) * AP + c];
#pragma unroll
            for (int jj = 0; jj < 4; jj++) bk[jj] = *(const float4*)&ks[(j0 + jj) * AP + c];
#pragma unroll
            for (int ii = 0; ii < 4; ii++)
#pragma unroll
                for (int jj = 0; jj < 4; jj++) {
                    s[ii][jj] = fmaf(aq[ii].x, bk[jj].x, s[ii][jj]);
                    s[ii][jj] = fmaf(aq[ii].y, bk[jj].y, s[ii][jj]);
                    s[ii][jj] = fmaf(aq[ii].z, bk[jj].z, s[ii][jj]);
                    s[ii][jj] = fmaf(aq[ii].w, bk[jj].w, s[ii][jj]);
                }
        }
#pragma unroll
        for (int ii = 0; ii < 4; ii++)
            *(float4*)&Ss[(i0 + ii) * AP + j0] =
                make_float4(s[ii][0], s[ii][1], s[ii][2], s[ii][3]);
    }
    __syncthreads();

    // softmax per row; warp handles 8 rows
    {
        const int lane = t & 31, warp = t >> 5;
#pragma unroll
        for (int rr = 0; rr < 8; rr++) {
            int row = (warp << 3) + rr;
            float x0 = Ss[row * AP + lane], x1 = Ss[row * AP + 32 + lane];
            float m = fmaxf(x0, x1);
#pragma unroll
            for (int o = 16; o > 0; o >>= 1)
                m = fmaxf(m, __shfl_xor_sync(0xffffffffu, m, o));
            float e0 = expf(x0 - m), e1 = expf(x1 - m);
            float su = e0 + e1;
#pragma unroll
            for (int o = 16; o > 0; o >>= 1)
                su += __shfl_xor_sync(0xffffffffu, su, o);
            float inv = 1.f / su;
            Ss[row * AP + lane] = e0 * inv;
            Ss[row * AP + 32 + lane] = e1 * inv;
        }
    }
    __syncthreads();

    // ctx = P @ V, 4 rows x 4 d per thread (d0 = j0)
    {
        float ctx[4][4];
#pragma unroll
        for (int i = 0; i < 4; i++)
#pragma unroll
            for (int j = 0; j < 4; j++) ctx[i][j] = 0.f;
        for (int j = 0; j < 64; j++) {
            float p[4];
#pragma unroll
            for (int ii = 0; ii < 4; ii++) p[ii] = Ss[(i0 + ii) * AP + j];
            float4 bv = *(const float4*)&vs[j * AP + j0];
#pragma unroll
            for (int ii = 0; ii < 4; ii++) {
                ctx[ii][0] = fmaf(p[ii], bv.x, ctx[ii][0]);
                ctx[ii][1] = fmaf(p[ii], bv.y, ctx[ii][1]);
                ctx[ii][2] = fmaf(p[ii], bv.z, ctx[ii][2]);
                ctx[ii][3] = fmaf(p[ii], bv.w, ctx[ii][3]);
            }
        }
#pragma unroll
        for (int ii = 0; ii < 4; ii++) {
            int i = i0 + ii;
            float* dst = vec + (size_t)(rowbase + (i >> 3) * W_ + (i & 7)) * C_
                             + (head << 6) + j0;
            *(float4*)dst = make_float4(ctx[ii][0], ctx[ii][1], ctx[ii][2], ctx[ii][3]);
        }
    }
}

// ---------------------------------------------------------------------------
// InstanceNorm stats: partial sum/sumsq per (b, channel) via atomics
// grid (64, B_), 256 threads: thread owns channels t and t+256 over 256 rows
// ---------------------------------------------------------------------------
__global__ __launch_bounds__(256) void stats_kernel(const float* __restrict__ h,
                                                    float* __restrict__ sums) {
    const int b = blockIdx.y, chunk = blockIdx.x, t = threadIdx.x;
    float s1a = 0.f, s2a = 0.f, s1b = 0.f, s2b = 0.f;
    const float* base = h + ((size_t)b * HW_ + (size_t)chunk * 256) * C2_;
    for (int r = 0; r < 256; r++) {
        float va = base[(size_t)r * C2_ + t];
        float vb = base[(size_t)r * C2_ + t + 256];
        s1a += va; s2a += va * va;
        s1b += vb; s2b += vb * vb;
    }
    atomicAdd(&sums[b * C2_ + t],              s1a);
    atomicAdd(&sums[4096 + b * C2_ + t],       s2a);
    atomicAdd(&sums[b * C2_ + t + 256],        s1b);
    atomicAdd(&sums[4096 + b * C2_ + t + 256], s2b);
}

__global__ void zero_kernel(float* __restrict__ p, int n) {
    int i = blockIdx.x * 256 + threadIdx.x;
    if (i < n) p[i] = 0.f;
}

// In-place: h = gelu_exact((h - mu) * rsqrt(var + eps))
__global__ __launch_bounds__(256) void norm_gelu_kernel(float* __restrict__ h,
                                                        const float* __restrict__ sums) {
    size_t idx = (size_t)blockIdx.x * 256 + threadIdx.x;   // < NT_*C2_
    int c2 = (int)(idx & (C2_ - 1));
    int b  = (int)(idx >> 23);                              // idx / (HW_*C2_) = idx / 2^23
    float mu  = sums[b * C2_ + c2] * (1.f / HW_);
    float var = sums[4096 + b * C2_ + c2] * (1.f / HW_) - mu * mu;
    float rstd = rsqrtf(var + 1e-5f);
    float v = (h[idx] - mu) * rstd;
    h[idx] = 0.5f * v * (1.f + erff(v * 0.70710678118654752f));
}

// bit = relu(mlp @ bit_w + bit_b); one warp per token
__global__ __launch_bounds__(256) void bit_kernel(const float* __restrict__ mlp,
                                                  const float* __restrict__ bw,
                                                  const float* __restrict__ bb,
                                                  float* __restrict__ bit) {
    const int warp = threadIdx.x >> 5, lane = threadIdx.x & 31;
    const size_t token = (size_t)blockIdx.x * 8 + warp;
    const float* row = mlp + token * C_;
    float s = 0.f;
#pragma unroll
    for (int k = 0; k < 8; k++) s = fmaf(row[lane + 32 * k], bw[lane + 32 * k], s);
#pragma unroll
    for (int o = 16; o > 0; o >>= 1) s += __shfl_xor_sync(0xffffffffu, s, o);
    if (lane == 0) bit[token] = fmaxf(s + bb[0], 0.f);
}

// out = x*sigmoid(wprod) + com*(1-sigmoid(wprod)); transpose vec token-major->CHW
__global__ __launch_bounds__(256) void combine_kernel(const float* __restrict__ x,
                                                      const float* __restrict__ vg,
                                                      const float* __restrict__ bg,
                                                      const float* __restrict__ vw,
                                                      const float* __restrict__ bwv,
                                                      float* __restrict__ out) {
    __shared__ float tg[32][33];
    __shared__ float tw[32][33];
    const int bh = blockIdx.z;
    const int b = bh >> 7, hh = bh & 127;
    const int cb = blockIdx.y << 5, wb = blockIdx.x << 5;
    const int tx = threadIdx.x, ty = threadIdx.y;   // (32, 8)
    const size_t tokbase = ((size_t)b * H_ + hh) * W_ + wb;
#pragma unroll
    for (int i = 0; i < 4; i++) {
        size_t off = (tokbase + ty + i * 8) * C_ + cb + tx;
        tg[ty + i * 8][tx] = vg[off];
        tw[ty + i * 8][tx] = vw[off];
    }
    __syncthreads();
#pragma unroll
    for (int i = 0; i < 4; i++) {
        int c = cb + ty + i * 8, w = wb + tx;
        size_t xi = (((size_t)b * C_ + c) * H_ + hh) * W_ + w;
        size_t si = (size_t)b * HW_ + hh * W_ + w;
        float com = bg[si] * tg[tx][ty + i * 8];
        float wpr = bwv[si] * tw[tx][ty + i * 8];
        float wm = 1.f / (1.f + expf(-wpr));
        out[xi] = x[xi] * wm + com * (1.f - wm);
    }
}

// ---------------------------------------------------------------------------
// Launch
// ---------------------------------------------------------------------------
extern "C" void kernel_launch(void* const* d_in, const int* in_sizes, int n_in,
                              void* d_out, int out_size) {
    (void)in_sizes; (void)n_in; (void)out_size;
    const float* x = (const float*)d_in[0];
    float* out = (float*)d_out;

    float *xt, *qkv, *hbuf, *mlp, *vec0, *vec1, *bit0, *bit1, *sums;
    cudaGetSymbolAddress((void**)&xt,   g_xt);
    cudaGetSymbolAddress((void**)&qkv,  g_qkv);
    cudaGetSymbolAddress((void**)&hbuf, g_h);
    cudaGetSymbolAddress((void**)&mlp,  g_mlp);
    cudaGetSymbolAddress((void**)&vec0, g_vec0);
    cudaGetSymbolAddress((void**)&vec1, g_vec1);
    cudaGetSymbolAddress((void**)&bit0, g_bit0);
    cudaGetSymbolAddress((void**)&bit1, g_bit1);
    cudaGetSymbolAddress((void**)&sums, g_sums);

    cudaFuncSetAttribute(attn_kernel, cudaFuncAttributeMaxDynamicSharedMemorySize,
                         4 * 64 * AP * (int)sizeof(float));

    transpose_kernel<<<dim3(4, 8, 1024), dim3(32, 8)>>>(x, xt);

    for (int br = 0; br < 2; br++) {
        const float* qkvw = (const float*)d_in[1 + br * 7];
        const float* fc1w = (const float*)d_in[2 + br * 7];
        const float* fc1b = (const float*)d_in[3 + br * 7];
        const float* fc2w = (const float*)d_in[4 + br * 7];
        const float* fc2b = (const float*)d_in[5 + br * 7];
        const float* bitw = (const float*)d_in[6 + br * 7];
        const float* bitb = (const float*)d_in[7 + br * 7];
        float* vec = br ? vec1 : vec0;
        float* bit = br ? bit1 : bit0;

        // qkv = xt @ Wqkv  (M=131072, N=768, K=256)
        sgemm<<<dim3(6, 1024), 256>>>(xt, qkvw, nullptr, qkv, 768, 256);
        // windowed MHSA -> vec (token-major)
        attn_kernel<<<dim3(4, 2048), 256, 4 * 64 * AP * (int)sizeof(float)>>>(qkv, vec);
        // h = xt @ Wfc1 + b  (N=512, K=256)
        sgemm<<<dim3(4, 1024), 256>>>(xt, fc1w, fc1b, hbuf, 512, 256);
        // InstanceNorm stats + normalize + exact GELU (in place)
        zero_kernel<<<32, 256>>>(sums, 2 * B_ * C2_);
        stats_kernel<<<dim3(64, B_), 256>>>(hbuf, sums);
        norm_gelu_kernel<<<262144, 256>>>(hbuf, sums);
        // mlp = h @ Wfc2 + b  (N=256, K=512)
        sgemm<<<dim3(2, 1024), 256>>>(hbuf, fc2w, fc2b, mlp, 256, 512);
        // bit = relu(mlp @ bit_w + bit_b)
        bit_kernel<<<16384, 256>>>(mlp, bitw, bitb, bit);
    }

    combine_kernel<<<dim3(4, 8, 1024), dim3(32, 8)>>>(x, vec0, bit0, vec1, bit1, out);
}

// round 3
// speedup vs baseline: 1.3143x; 1.3143x over previous
#include <cuda_runtime.h>
#include <math.h>
#include <stdint.h>

// Problem shape constants
#define B_   8
#define C_   256
#define H_   128
#define W_   128
#define HW_  16384          // H_*W_
#define NT_  131072         // B_*HW_
#define C2_  512            // 2*C_

// ---------------------------------------------------------------------------
// Scratch (device globals; allocation-free rule)
// ---------------------------------------------------------------------------
__device__ float g_xt  [NT_ * C_];
__device__ float g_qkv [NT_ * 3 * C_];
__device__ float g_h   [NT_ * C2_];
__device__ float g_mlp [NT_ * C_];
__device__ float g_vec0[NT_ * C_];
__device__ float g_vec1[NT_ * C_];
__device__ float g_bit0[NT_];
__device__ float g_bit1[NT_];
__device__ float g_sums[2 * B_ * C2_];

// ---------------------------------------------------------------------------
// Transpose x (B,C,H,W) -> xt (B,H,W,C)
// ---------------------------------------------------------------------------
__global__ __launch_bounds__(256) void transpose_kernel(const float* __restrict__ x,
                                                        float* __restrict__ xt) {
    __shared__ float tile[32][33];
    const int bh = blockIdx.z;
    const int b  = bh >> 7, hh = bh & 127;
    const int cb = blockIdx.y << 5, wb = blockIdx.x << 5;
    const int tx = threadIdx.x, ty = threadIdx.y;     // (32, 8)
    const float* src = x + (((size_t)b * C_ + cb) * H_ + hh) * W_ + wb;
#pragma unroll
    for (int i = 0; i < 4; i++)
        tile[ty + i * 8][tx] = src[(size_t)(ty + i * 8) * HW_ + tx];
    __syncthreads();
    float* dst = xt + (((size_t)b * H_ + hh) * W_ + wb) * C_ + cb;
#pragma unroll
    for (int i = 0; i < 4; i++)
        dst[(size_t)(ty + i * 8) * C_ + tx] = tile[tx][ty + i * 8];
}

// ---------------------------------------------------------------------------
// TF32 tensor-core GEMM: C = A(MxK) * B(KxN) [+ bias], row-major.
// Tile 128x128x32, 8 warps (2x4), warp tile 64x32, mma.m16n8k8.tf32.
// fp32->tf32 via cvt.rna at the STS stage (unbiased rounding).
// Smem: As[m][36] (bank 4m+k), Bs[k][132] (bank 4k+n): conflict-free frags.
// Dynamic smem: 2*(128*36 + 32*132)*4 = 70656 B. Grid (N/128, M/128), 256 thr.
// ---------------------------------------------------------------------------
__device__ __forceinline__ float to_tf32(float x) {
    uint32_t u;
    asm("cvt.rna.tf32.f32 %0, %1;" : "=r"(u) : "f"(x));
    return __uint_as_float(u);
}

#define MMA_TF32(Cr, A0, A1, A2, A3, B0, B1)                                   \
    asm volatile(                                                              \
        "mma.sync.aligned.m16n8k8.row.col.f32.tf32.tf32.f32 "                  \
        "{%0,%1,%2,%3}, {%4,%5,%6,%7}, {%8,%9}, {%0,%1,%2,%3};"                \
        : "+f"(Cr[0]), "+f"(Cr[1]), "+f"(Cr[2]), "+f"(Cr[3])                   \
        : "r"(A0), "r"(A1), "r"(A2), "r"(A3), "r"(B0), "r"(B1))

#define AS_STRIDE 36
#define BS_STRIDE 132
#define AS_BUF (128 * AS_STRIDE)   // 4608 floats
#define BS_BUF (32 * BS_STRIDE)    // 4224 floats
#define SGEMM_SMEM ((2 * (AS_BUF + BS_BUF)) * 4)   // 70656 bytes

__global__ __launch_bounds__(256) void sgemm_tf32(const float* __restrict__ A,
                                                  const float* __restrict__ Bm,
                                                  const float* __restrict__ bias,
                                                  float* __restrict__ Cm,
                                                  int N, int K) {
    extern __shared__ float sm[];
    float* AsBase = sm;                    // [2][128][36]
    float* BsBase = sm + 2 * AS_BUF;       // [2][32][132]

    const int tid  = threadIdx.x;
    const int lane = tid & 31, wid = tid >> 5;
    const int warp_m = wid >> 2, warp_n = wid & 3;
    const int bm = blockIdx.y << 7, bn = blockIdx.x << 7;
    const int m0 = warp_m << 6, n0 = warp_n << 5;
    const int lr = lane >> 2, lc = lane & 3;    // fragment row-group / k-quad

    float c[4][4][4];
#pragma unroll
    for (int mt = 0; mt < 4; mt++)
#pragma unroll
        for (int nt = 0; nt < 4; nt++)
#pragma unroll
            for (int r = 0; r < 4; r++) c[mt][nt][r] = 0.f;

    float4 la[4], lb[4];

    auto load_tiles = [&](int k0) {
#pragma unroll
        for (int r = 0; r < 4; r++) {
            int idx = tid + (r << 8);
            int m = idx >> 3, kq = (idx & 7) << 2;
            la[r] = *(const float4*)(A + (size_t)(bm + m) * K + k0 + kq);
            int kb = idx >> 5, nq = (idx & 31) << 2;
            lb[r] = *(const float4*)(Bm + (size_t)(k0 + kb) * N + bn + nq);
        }
    };
    auto store_tiles = [&](int buf) {
        float* As = AsBase + buf * AS_BUF;
        float* Bs = BsBase + buf * BS_BUF;
#pragma unroll
        for (int r = 0; r < 4; r++) {
            int idx = tid + (r << 8);
            int m = idx >> 3, kq = (idx & 7) << 2;
            float4 va = la[r];
            *(float4*)&As[m * AS_STRIDE + kq] =
                make_float4(to_tf32(va.x), to_tf32(va.y), to_tf32(va.z), to_tf32(va.w));
            int kb = idx >> 5, nq = (idx & 31) << 2;
            float4 vb = lb[r];
            *(float4*)&Bs[kb * BS_STRIDE + nq] =
                make_float4(to_tf32(vb.x), to_tf32(vb.y), to_tf32(vb.z), to_tf32(vb.w));
        }
    };
    auto compute = [&](int buf) {
        const float* As = AsBase + buf * AS_BUF;
        const float* Bs = BsBase + buf * BS_BUF;
#pragma unroll
        for (int kk = 0; kk < 32; kk += 8) {
            uint32_t bf[4][2];
#pragma unroll
            for (int nt = 0; nt < 4; nt++) {
                int n = n0 + (nt << 3) + lr;
                bf[nt][0] = __float_as_uint(Bs[(kk + lc) * BS_STRIDE + n]);
                bf[nt][1] = __float_as_uint(Bs[(kk + 4 + lc) * BS_STRIDE + n]);
            }
#pragma unroll
            for (int mt = 0; mt < 4; mt++) {
                int mrow = m0 + (mt << 4) + lr;
                uint32_t a0 = __float_as_uint(As[mrow * AS_STRIDE + kk + lc]);
                uint32_t a1 = __float_as_uint(As[(mrow + 8) * AS_STRIDE + kk + lc]);
                uint32_t a2 = __float_as_uint(As[mrow * AS_STRIDE + kk + 4 + lc]);
                uint32_t a3 = __float_as_uint(As[(mrow + 8) * AS_STRIDE + kk + 4 + lc]);
#pragma unroll
                for (int nt = 0; nt < 4; nt++)
                    MMA_TF32(c[mt][nt], a0, a1, a2, a3, bf[nt][0], bf[nt][1]);
            }
        }
    };

    load_tiles(0);
    store_tiles(0);
    __syncthreads();

    int buf = 0;
    for (int k0 = 32; k0 < K; k0 += 32) {
        load_tiles(k0);
        compute(buf);
        store_tiles(buf ^ 1);
        __syncthreads();
        buf ^= 1;
    }
    compute(buf);

    // Epilogue
#pragma unroll
    for (int nt = 0; nt < 4; nt++) {
        int col = bn + n0 + (nt << 3) + (lc << 1);
        float b0 = bias ? bias[col]     : 0.f;
        float b1 = bias ? bias[col + 1] : 0.f;
#pragma unroll
        for (int mt = 0; mt < 4; mt++) {
            int row = bm + m0 + (mt << 4) + lr;
            float2 v0 = make_float2(c[mt][nt][0] + b0, c[mt][nt][1] + b1);
            float2 v1 = make_float2(c[mt][nt][2] + b0, c[mt][nt][3] + b1);
            *(float2*)&Cm[(size_t)row * N + col]       = v0;
            *(float2*)&Cm[(size_t)(row + 8) * N + col] = v1;
        }
    }
}

// ---------------------------------------------------------------------------
// Windowed attention: block = (head, window). 64 tokens, hd=64, scale=1/8.
// Dynamic smem: q,k,v,S each [64][68] floats = 69632 B.
// ---------------------------------------------------------------------------
#define AP 68
__global__ __launch_bounds__(256) void attn_kernel(const float* __restrict__ qkv,
                                                   float* __restrict__ vec) {
    extern __shared__ float sm[];
    float* qs = sm;
    float* ks = sm + 64 * AP;
    float* vs = sm + 2 * 64 * AP;
    float* Ss = sm + 3 * 64 * AP;

    const int t = threadIdx.x;
    const int head = blockIdx.x;
    const int win  = blockIdx.y;
    const int b = win >> 8, wx = (win >> 4) & 15, wy = win & 15;
    const int rowbase = b * HW_ + ((wx << 3) * W_) + (wy << 3);

#pragma unroll
    for (int r = 0; r < 4; r++) {
        int idx = t + (r << 8);
        int i = idx >> 4, fc = (idx & 15) << 2;
        const float* src = qkv + (size_t)(rowbase + (i >> 3) * W_ + (i & 7)) * 768
                               + (head << 6) + fc;
        float4 qv = *(const float4*)src;
        float4 kv = *(const float4*)(src + 256);
        float4 vv = *(const float4*)(src + 512);
        qv.x *= 0.125f; qv.y *= 0.125f; qv.z *= 0.125f; qv.w *= 0.125f;
        *(float4*)&qs[i * AP + fc] = qv;
        *(float4*)&ks[i * AP + fc] = kv;
        *(float4*)&vs[i * AP + fc] = vv;
    }
    __syncthreads();

    const int rid = t >> 4, cid = t & 15;
    const int i0 = rid << 2, j0 = cid << 2;

    {
        float s[4][4];
#pragma unroll
        for (int i = 0; i < 4; i++)
#pragma unroll
            for (int j = 0; j < 4; j++) s[i][j] = 0.f;
        for (int cidx = 0; cidx < 64; cidx += 4) {
            float4 aq[4], bk[4];
#pragma unroll
            for (int ii = 0; ii < 4; ii++) aq[ii] = *(const float4*)&qs[(i0 + ii) * AP + cidx];
#pragma unroll
            for (int jj = 0; jj < 4; jj++) bk[jj] = *(const float4*)&ks[(j0 + jj) * AP + cidx];
#pragma unroll
            for (int ii = 0; ii < 4; ii++)
#pragma unroll
                for (int jj = 0; jj < 4; jj++) {
                    s[ii][jj] = fmaf(aq[ii].x, bk[jj].x, s[ii][jj]);
                    s[ii][jj] = fmaf(aq[ii].y, bk[jj].y, s[ii][jj]);
                    s[ii][jj] = fmaf(aq[ii].z, bk[jj].z, s[ii][jj]);
                    s[ii][jj] = fmaf(aq[ii].w, bk[jj].w, s[ii][jj]);
                }
        }
#pragma unroll
        for (int ii = 0; ii < 4; ii++)
            *(float4*)&Ss[(i0 + ii) * AP + j0] =
                make_float4(s[ii][0], s[ii][1], s[ii][2], s[ii][3]);
    }
    __syncthreads();

    {
        const int lane = t & 31, warp = t >> 5;
#pragma unroll
        for (int rr = 0; rr < 8; rr++) {
            int row = (warp << 3) + rr;
            float x0 = Ss[row * AP + lane], x1 = Ss[row * AP + 32 + lane];
            float m = fmaxf(x0, x1);
#pragma unroll
            for (int o = 16; o > 0; o >>= 1)
                m = fmaxf(m, __shfl_xor_sync(0xffffffffu, m, o));
            float e0 = expf(x0 - m), e1 = expf(x1 - m);
            float su = e0 + e1;
#pragma unroll
            for (int o = 16; o > 0; o >>= 1)
                su += __shfl_xor_sync(0xffffffffu, su, o);
            float inv = 1.f / su;
            Ss[row * AP + lane] = e0 * inv;
            Ss[row * AP + 32 + lane] = e1 * inv;
        }
    }
    __syncthreads();

    {
        float ctx[4][4];
#pragma unroll
        for (int i = 0; i < 4; i++)
#pragma unroll
            for (int j = 0; j < 4; j++) ctx[i][j] = 0.f;
        for (int j = 0; j < 64; j++) {
            float p[4];
#pragma unroll
            for (int ii = 0; ii < 4; ii++) p[ii] = Ss[(i0 + ii) * AP + j];
            float4 bv = *(const float4*)&vs[j * AP + j0];
#pragma unroll
            for (int ii = 0; ii < 4; ii++) {
                ctx[ii][0] = fmaf(p[ii], bv.x, ctx[ii][0]);
                ctx[ii][1] = fmaf(p[ii], bv.y, ctx[ii][1]);
                ctx[ii][2] = fmaf(p[ii], bv.z, ctx[ii][2]);
                ctx[ii][3] = fmaf(p[ii], bv.w, ctx[ii][3]);
            }
        }
#pragma unroll
        for (int ii = 0; ii < 4; ii++) {
            int i = i0 + ii;
            float* dst = vec + (size_t)(rowbase + (i >> 3) * W_ + (i & 7)) * C_
                             + (head << 6) + j0;
            *(float4*)dst = make_float4(ctx[ii][0], ctx[ii][1], ctx[ii][2], ctx[ii][3]);
        }
    }
}

// ---------------------------------------------------------------------------
// InstanceNorm stats
// ---------------------------------------------------------------------------
__global__ __launch_bounds__(256) void stats_kernel(const float* __restrict__ h,
                                                    float* __restrict__ sums) {
    const int b = blockIdx.y, chunk = blockIdx.x, t = threadIdx.x;
    float s1a = 0.f, s2a = 0.f, s1b = 0.f, s2b = 0.f;
    const float* base = h + ((size_t)b * HW_ + (size_t)chunk * 256) * C2_;
    for (int r = 0; r < 256; r++) {
        float va = base[(size_t)r * C2_ + t];
        float vb = base[(size_t)r * C2_ + t + 256];
        s1a += va; s2a += va * va;
        s1b += vb; s2b += vb * vb;
    }
    atomicAdd(&sums[b * C2_ + t],              s1a);
    atomicAdd(&sums[4096 + b * C2_ + t],       s2a);
    atomicAdd(&sums[b * C2_ + t + 256],        s1b);
    atomicAdd(&sums[4096 + b * C2_ + t + 256], s2b);
}

__global__ void zero_kernel(float* __restrict__ p, int n) {
    int i = blockIdx.x * 256 + threadIdx.x;
    if (i < n) p[i] = 0.f;
}

__global__ __launch_bounds__(256) void norm_gelu_kernel(float* __restrict__ h,
                                                        const float* __restrict__ sums) {
    size_t idx = (size_t)blockIdx.x * 256 + threadIdx.x;
    int c2 = (int)(idx & (C2_ - 1));
    int b  = (int)(idx >> 23);
    float mu  = sums[b * C2_ + c2] * (1.f / HW_);
    float var = sums[4096 + b * C2_ + c2] * (1.f / HW_) - mu * mu;
    float rstd = rsqrtf(var + 1e-5f);
    float v = (h[idx] - mu) * rstd;
    h[idx] = 0.5f * v * (1.f + erff(v * 0.70710678118654752f));
}

__global__ __launch_bounds__(256) void bit_kernel(const float* __restrict__ mlp,
                                                  const float* __restrict__ bw,
                                                  const float* __restrict__ bb,
                                                  float* __restrict__ bit) {
    const int warp = threadIdx.x >> 5, lane = threadIdx.x & 31;
    const size_t token = (size_t)blockIdx.x * 8 + warp;
    const float* row = mlp + token * C_;
    float s = 0.f;
#pragma unroll
    for (int k = 0; k < 8; k++) s = fmaf(row[lane + 32 * k], bw[lane + 32 * k], s);
#pragma unroll
    for (int o = 16; o > 0; o >>= 1) s += __shfl_xor_sync(0xffffffffu, s, o);
    if (lane == 0) bit[token] = fmaxf(s + bb[0], 0.f);
}

__global__ __launch_bounds__(256) void combine_kernel(const float* __restrict__ x,
                                                      const float* __restrict__ vg,
                                                      const float* __restrict__ bg,
                                                      const float* __restrict__ vw,
                                                      const float* __restrict__ bwv,
                                                      float* __restrict__ out) {
    __shared__ float tg[32][33];
    __shared__ float tw[32][33];
    const int bh = blockIdx.z;
    const int b = bh >> 7, hh = bh & 127;
    const int cb = blockIdx.y << 5, wb = blockIdx.x << 5;
    const int tx = threadIdx.x, ty = threadIdx.y;   // (32, 8)
    const size_t tokbase = ((size_t)b * H_ + hh) * W_ + wb;
#pragma unroll
    for (int i = 0; i < 4; i++) {
        size_t off = (tokbase + ty + i * 8) * C_ + cb + tx;
        tg[ty + i * 8][tx] = vg[off];
        tw[ty + i * 8][tx] = vw[off];
    }
    __syncthreads();
#pragma unroll
    for (int i = 0; i < 4; i++) {
        int cc = cb + ty + i * 8, w = wb + tx;
        size_t xi = (((size_t)b * C_ + cc) * H_ + hh) * W_ + w;
        size_t si = (size_t)b * HW_ + hh * W_ + w;
        float com = bg[si] * tg[tx][ty + i * 8];
        float wpr = bwv[si] * tw[tx][ty + i * 8];
        float wm = 1.f / (1.f + expf(-wpr));
        out[xi] = x[xi] * wm + com * (1.f - wm);
    }
}

// ---------------------------------------------------------------------------
// Launch
// ---------------------------------------------------------------------------
extern "C" void kernel_launch(void* const* d_in, const int* in_sizes, int n_in,
                              void* d_out, int out_size) {
    (void)in_sizes; (void)n_in; (void)out_size;
    const float* x = (const float*)d_in[0];
    float* out = (float*)d_out;

    float *xt, *qkv, *hbuf, *mlp, *vec0, *vec1, *bit0, *bit1, *sums;
    cudaGetSymbolAddress((void**)&xt,   g_xt);
    cudaGetSymbolAddress((void**)&qkv,  g_qkv);
    cudaGetSymbolAddress((void**)&hbuf, g_h);
    cudaGetSymbolAddress((void**)&mlp,  g_mlp);
    cudaGetSymbolAddress((void**)&vec0, g_vec0);
    cudaGetSymbolAddress((void**)&vec1, g_vec1);
    cudaGetSymbolAddress((void**)&bit0, g_bit0);
    cudaGetSymbolAddress((void**)&bit1, g_bit1);
    cudaGetSymbolAddress((void**)&sums, g_sums);

    cudaFuncSetAttribute(attn_kernel, cudaFuncAttributeMaxDynamicSharedMemorySize,
                         4 * 64 * AP * (int)sizeof(float));
    cudaFuncSetAttribute(sgemm_tf32, cudaFuncAttributeMaxDynamicSharedMemorySize,
                         SGEMM_SMEM);

    transpose_kernel<<<dim3(4, 8, 1024), dim3(32, 8)>>>(x, xt);

    for (int br = 0; br < 2; br++) {
        const float* qkvw = (const float*)d_in[1 + br * 7];
        const float* fc1w = (const float*)d_in[2 + br * 7];
        const float* fc1b = (const float*)d_in[3 + br * 7];
        const float* fc2w = (const float*)d_in[4 + br * 7];
        const float* fc2b = (const float*)d_in[5 + br * 7];
        const float* bitw = (const float*)d_in[6 + br * 7];
        const float* bitb = (const float*)d_in[7 + br * 7];
        float* vec = br ? vec1 : vec0;
        float* bit = br ? bit1 : bit0;

        // qkv = xt @ Wqkv  (M=131072, N=768, K=256)
        sgemm_tf32<<<dim3(6, 1024), 256, SGEMM_SMEM>>>(xt, qkvw, nullptr, qkv, 768, 256);
        // windowed MHSA -> vec (token-major)
        attn_kernel<<<dim3(4, 2048), 256, 4 * 64 * AP * (int)sizeof(float)>>>(qkv, vec);
        // h = xt @ Wfc1 + b  (N=512, K=256)
        sgemm_tf32<<<dim3(4, 1024), 256, SGEMM_SMEM>>>(xt, fc1w, fc1b, hbuf, 512, 256);
        // InstanceNorm stats + normalize + exact GELU (in place)
        zero_kernel<<<32, 256>>>(sums, 2 * B_ * C2_);
        stats_kernel<<<dim3(64, B_), 256>>>(hbuf, sums);
        norm_gelu_kernel<<<262144, 256>>>(hbuf, sums);
        // mlp = h @ Wfc2 + b  (N=256, K=512)
        sgemm_tf32<<<dim3(2, 1024), 256, SGEMM_SMEM>>>(hbuf, fc2w, fc2b, mlp, 256, 512);
        // bit = relu(mlp @ bit_w + bit_b)
        bit_kernel<<<16384, 256>>>(mlp, bitw, bitb, bit);
    }

    combine_kernel<<<dim3(4, 8, 1024), dim3(32, 8)>>>(x, vec0, bit0, vec1, bit1, out);
}